// round 17
// baseline (speedup 1.0000x reference)
#include <cuda_runtime.h>
#include <cuda_bf16.h>
#include <cuda_fp16.h>
#include <cstdint>
#include <cstddef>

#define BATCH 2
#define SEQ 2048
#define SPAD 2050
#define DMODEL 1024
#define NHEAD 16
#define PADROWS (BATCH * SPAD)

// ===========================================================================
// Scratch
// ===========================================================================
__device__ __nv_bfloat16 g_hi[2 * PADROWS * DMODEL];   // q,k act split hi
__device__ __nv_bfloat16 g_lo[2 * PADROWS * DMODEL];
__device__ __half        g_vact[PADROWS * DMODEL];     // v activation fp16
__device__ __half        g_qfh[PADROWS * DMODEL];      // projected q fp16 hi
__device__ __half        g_qfl[PADROWS * DMODEL];      // projected q fp16 lo
__device__ __half        g_kf[PADROWS * DMODEL];       // projected k fp16 single
__device__ __half        g_vf[PADROWS * DMODEL];       // projected v fp16
__device__ __half        g_aof[PADROWS * DMODEL];      // attention out fp16
__device__ __nv_bfloat16 g_Wqc[DMODEL * 6144];   // {Whi x3 taps, Wlo x3 taps}
__device__ __nv_bfloat16 g_Wkc[DMODEL * 6144];
__device__ __half        g_Wvf[DMODEL * 1024];   // fp16 single
__device__ __half        g_Wcf[DMODEL * 1024];
__device__ float g_bq[DMODEL], g_bk[DMODEL], g_bv[DMODEL], g_bc[DMODEL];

// ===========================================================================
// PTX helpers
// ===========================================================================
__device__ __forceinline__ uint32_t smem_to_u32(const void* p) {
    uint32_t a;
    asm("{ .reg .u64 t; cvta.to.shared.u64 t, %1; cvt.u32.u64 %0, t; }" : "=r"(a) : "l"(p));
    return a;
}
__device__ __forceinline__ void cp16(uint32_t dst, const void* src) {
    asm volatile("cp.async.cg.shared.global [%0], [%1], 16;" :: "r"(dst), "l"(src));
}
__device__ __forceinline__ void ldsm_x4(uint32_t* r, uint32_t addr) {
    asm volatile("ldmatrix.sync.aligned.m8n8.x4.shared.b16 {%0,%1,%2,%3}, [%4];"
        : "=r"(r[0]), "=r"(r[1]), "=r"(r[2]), "=r"(r[3]) : "r"(addr));
}
__device__ __forceinline__ void ldsm_x4_t(uint32_t* r, uint32_t addr) {
    asm volatile("ldmatrix.sync.aligned.m8n8.x4.trans.shared.b16 {%0,%1,%2,%3}, [%4];"
        : "=r"(r[0]), "=r"(r[1]), "=r"(r[2]), "=r"(r[3]) : "r"(addr));
}
__device__ __forceinline__ void mma_bf16(float* d, const uint32_t* a, const uint32_t* b) {
    asm volatile(
        "mma.sync.aligned.m16n8k16.row.col.f32.bf16.bf16.f32 "
        "{%0,%1,%2,%3}, {%4,%5,%6,%7}, {%8,%9}, {%0,%1,%2,%3};"
        : "+f"(d[0]), "+f"(d[1]), "+f"(d[2]), "+f"(d[3])
        : "r"(a[0]), "r"(a[1]), "r"(a[2]), "r"(a[3]), "r"(b[0]), "r"(b[1]));
}
__device__ __forceinline__ void mma_f16(float* d, const uint32_t* a, const uint32_t* b) {
    asm volatile(
        "mma.sync.aligned.m16n8k16.row.col.f32.f16.f16.f32 "
        "{%0,%1,%2,%3}, {%4,%5,%6,%7}, {%8,%9}, {%0,%1,%2,%3};"
        : "+f"(d[0]), "+f"(d[1]), "+f"(d[2]), "+f"(d[3])
        : "r"(a[0]), "r"(a[1]), "r"(a[2]), "r"(a[3]), "r"(b[0]), "r"(b[1]));
}
__device__ __forceinline__ uint32_t pack_bf16(float lo, float hi) {
    uint32_t r; asm("cvt.rn.bf16x2.f32 %0, %1, %2;" : "=r"(r) : "f"(hi), "f"(lo)); return r;
}
__device__ __forceinline__ uint32_t pack_f16(float lo, float hi) {
    uint32_t r; asm("cvt.rn.f16x2.f32 %0, %1, %2;" : "=r"(r) : "f"(hi), "f"(lo)); return r;
}
__device__ __forceinline__ float f_low(uint32_t r)  { return __uint_as_float(r << 16); }
__device__ __forceinline__ float f_high(uint32_t r) { return __uint_as_float(r & 0xffff0000u); }
__device__ __forceinline__ float ex2f(float x) {
    float r; asm("ex2.approx.f32 %0, %1;" : "=f"(r) : "f"(x)); return r;
}
__device__ __forceinline__ void split_pair(float v0, float v1, uint32_t& h2, uint32_t& l2) {
    h2 = pack_bf16(v0, v1);
    l2 = pack_bf16(v0 - f_low(h2), v1 - f_high(h2));
}
__device__ __forceinline__ void split_pair_f16(float v0, float v1, uint32_t& h2, uint32_t& l2) {
    h2 = pack_f16(v0, v1);
    __half2 p = *(__half2*)&h2;
    l2 = pack_f16(v0 - __low2float(p), v1 - __high2float(p));
}

// ===========================================================================
// Fused prep: q,k -> bf16 hi/lo; v -> fp16. grid (1, 513, 6), 4 rows/block
// ===========================================================================
struct SArgs {
    const float* X[3];
    __nv_bfloat16* hi[2]; __nv_bfloat16* lo[2];
    __half* vf;
};

__global__ void split_act_all(SArgs sa) {
    int z = blockIdx.z;
    int t = z >> 1, b = z & 1;
    int c = threadIdx.x << 2;
#pragma unroll
    for (int ry = 0; ry < 4; ry++) {
        int y = (blockIdx.y << 2) + ry;
        if (y >= SPAD) break;
        float4 v = make_float4(0.f, 0.f, 0.f, 0.f);
        if (y >= 1 && y <= SEQ)
            v = *(const float4*)&sa.X[t][(((size_t)b * SEQ + (y - 1)) << 10) + c];
        size_t o = (((size_t)b * SPAD + y) << 10) + c;
        if (t < 2) {
            uint32_t h0, l0, h1, l1;
            split_pair(v.x, v.y, h0, l0);
            split_pair(v.z, v.w, h1, l1);
            *(uint2*)&sa.hi[t][o] = make_uint2(h0, h1);
            *(uint2*)&sa.lo[t][o] = make_uint2(l0, l1);
        } else {
            *(uint2*)&sa.vf[o] = make_uint2(pack_f16(v.x, v.y), pack_f16(v.z, v.w));
        }
    }
}

// ===========================================================================
// Fused prep: weight transforms. grid (1024, 4).
// ===========================================================================
struct WArgs {
    const float* w[4]; const float* b[4];
    void* out[4]; float* bP[4];
    int KS[4]; int perm[4]; int f16[4];
};

__global__ void transform_w_all(WArgs wa) {
    int ws = blockIdx.y;
    int c = blockIdx.x;
    int i = threadIdx.x << 2;
    int KS = wa.KS[ws];
    int o = wa.perm[ws] ? ((c & 63) * 16 + (c >> 6)) : c;
    const float* src = wa.w[ws] + ((size_t)o * 1024 + i) * KS;
    if (wa.f16[ws]) {
        __half* Wf = (__half*)wa.out[ws];
        for (int tap = 0; tap < KS; tap++) {
            float v0 = src[0 * KS + tap], v1 = src[1 * KS + tap];
            float v2 = src[2 * KS + tap], v3 = src[3 * KS + tap];
            *(uint2*)&Wf[(size_t)c * (KS << 10) + ((size_t)tap << 10) + i] =
                make_uint2(pack_f16(v0, v1), pack_f16(v2, v3));
        }
    } else {
        __nv_bfloat16* Wcat = (__nv_bfloat16*)wa.out[ws];
        const int W2 = (KS << 1) << 10;
        for (int tap = 0; tap < KS; tap++) {
            float v0 = src[0 * KS + tap], v1 = src[1 * KS + tap];
            float v2 = src[2 * KS + tap], v3 = src[3 * KS + tap];
            uint32_t h0, l0, h1, l1;
            split_pair(v0, v1, h0, l0);
            split_pair(v2, v3, h1, l1);
            *(uint2*)&Wcat[(size_t)c * W2 + ((size_t)tap << 10) + i] = make_uint2(h0, h1);
            *(uint2*)&Wcat[(size_t)c * W2 + ((size_t)(KS + tap) << 10) + i] = make_uint2(l0, l1);
        }
    }
    if (threadIdx.x == 0) wa.bP[ws][c] = wa.b[ws][o];
}

// ===========================================================================
// q/k conv-GEMM (R7 shape): BM=256, BN=128, wide B tiles (2 segments,
// 272B pitch), 1 CTA/SM, 8 warps (4m x 2n), warp tile 64x64.
// 3-term bf16 schedule, J = 48 (half the sync points of the BM=128 version).
// z=0: q -> split fp16 (Chi+Clo). z=1: k -> single fp16.
// ===========================================================================
#define QK_ATILE 37152                 // 258 rows * 144 B
#define QK_AREG (4 * QK_ATILE)         // hi/lo x double buffer = 148608
#define QK_BTILE 34816                 // 128 rows * 272 B
#define QK_SMEM (QK_AREG + 2 * QK_BTILE)   // 218240

struct QKArgs {
    const __nv_bfloat16* Ah[2]; const __nv_bfloat16* Al[2];
    const __nv_bfloat16* Bw[2]; const float* bias[2];
    __half* Ch[2]; __half* Cl[2];
    int outMode[2];   // 0: split fp16, 1: single fp16
};

__global__ void __launch_bounds__(256, 1) gemm_qk_kernel(QKArgs ga)
{
    extern __shared__ __align__(128) char smem[];
    const uint32_t sb = smem_to_u32(smem);
    const int tid = threadIdx.x, wid = tid >> 5, lane = tid & 31;
    const int z = blockIdx.z;
    const __nv_bfloat16* __restrict__ Ahi = ga.Ah[z];
    const __nv_bfloat16* __restrict__ Alo = ga.Al[z];
    const __nv_bfloat16* __restrict__ Bw  = ga.Bw[z];
    const float* __restrict__ bP = ga.bias[z];
    const int KS = 3;

    const int row0 = blockIdx.y << 8;            // 256 rows
    const int col0 = blockIdx.x << 7;            // 128 cols
    const int bb = row0 >> 11;
    const size_t base = (size_t)bb * SPAD + (row0 & 2047);
    const int NPAIR = KS;                        // 3 B-tile pairs per chunk
    const int Kp = (KS << 1) << 10;              // 6144
    const int J = KS << 4;                       // 48
    const int wm = (wid >> 1) << 6;              // 0,64,128,192
    const int wn = (wid & 1) << 6;               // 0,64

    auto load_A = [&](int ch) {
        uint32_t dst = sb + (uint32_t)(ch & 1) * (2 * QK_ATILE);
        int c0 = ch << 6;
#pragma unroll
        for (int l = 0; l < 17; l++) {
            int idx = tid + (l << 8);
            if (idx < 4128) {
                int mat = 0;
                if (idx >= 2064) { idx -= 2064; mat = 1; }
                int r = idx >> 3, jc = idx & 7;
                const __nv_bfloat16* src = (mat ? Alo : Ahi)
                    + (((base + r) << 10) + c0 + (jc << 3));
                cp16(dst + (uint32_t)(mat * QK_ATILE + r * 144 + (jc << 4)), src);
            }
        }
    };
    auto load_B = [&](int j, int jp, int ch) {
        uint32_t dst = sb + QK_AREG + (uint32_t)(j & 1) * QK_BTILE;
#pragma unroll
        for (int l = 0; l < 8; l++) {
            int idx = tid + (l << 8);
            int r = idx >> 4, jc = idx & 15;
            int seg = (jp << 1) + (jc >> 3);
            size_t koff = ((size_t)seg << 10) + (ch << 6) + ((jc & 7) << 3);
            cp16(dst + (uint32_t)(r * 272 + (jc << 4)),
                 Bw + (size_t)(col0 + r) * Kp + koff);
        }
    };

    float acc[4][8][4];
#pragma unroll
    for (int mt = 0; mt < 4; mt++)
#pragma unroll
        for (int nt = 0; nt < 8; nt++)
#pragma unroll
            for (int e = 0; e < 4; e++) acc[mt][nt][e] = 0.f;

    load_A(0);
    load_B(0, 0, 0);
    asm volatile("cp.async.commit_group;");

    int jp = 0, ch = 0;
    for (int j = 0; j < J; j++) {
        if (jp == 0 && ch + 1 < 16) load_A(ch + 1);
        if (j + 1 < J) {
            int jp2 = jp + 1, ch2 = ch;
            if (jp2 == NPAIR) { jp2 = 0; ch2++; }
            load_B(j + 1, jp2, ch2);
            asm volatile("cp.async.commit_group;");
            asm volatile("cp.async.wait_group 1;");
        } else {
            asm volatile("cp.async.commit_group;");
            asm volatile("cp.async.wait_group 0;");
        }
        __syncthreads();

        const uint32_t AsmHi = sb + (uint32_t)(ch & 1) * (2 * QK_ATILE);
        const uint32_t AsmLo = AsmHi + QK_ATILE;
        const uint32_t Bsm = sb + QK_AREG + (uint32_t)(j & 1) * QK_BTILE;

#pragma unroll
        for (int half = 0; half < 2; half++) {
            const int s = (jp << 1) + half;
            const int tap = (s < KS) ? s : s - KS;
            const bool doLo = (s < KS);
            const uint32_t Bh = Bsm + (uint32_t)(half << 7);   // +128B per 64-K half

#pragma unroll
            for (int kk = 0; kk < 64; kk += 16) {
                uint32_t b[4][4], a[4][4];
#pragma unroll
                for (int g = 0; g < 4; g++) {
                    int nrow = wn + g * 16 + (lane & 7) + ((lane >> 4) << 3);
                    ldsm_x4(b[g], Bh + (uint32_t)(nrow * 272 + (kk + (((lane >> 3) & 1) << 3)) * 2));
                }
#pragma unroll
                for (int mt = 0; mt < 4; mt++)
                    ldsm_x4(a[mt], AsmHi + (uint32_t)((wm + tap + mt * 16 + (lane & 15)) * 144
                            + ((lane >> 4) << 4) + kk * 2));
#pragma unroll
                for (int mt = 0; mt < 4; mt++)
#pragma unroll
                    for (int g = 0; g < 4; g++) {
                        mma_bf16(acc[mt][2 * g + 0], a[mt], &b[g][0]);
                        mma_bf16(acc[mt][2 * g + 1], a[mt], &b[g][2]);
                    }
                if (doLo) {
#pragma unroll
                    for (int mt = 0; mt < 4; mt++)
                        ldsm_x4(a[mt], AsmLo + (uint32_t)((wm + tap + mt * 16 + (lane & 15)) * 144
                                + ((lane >> 4) << 4) + kk * 2));
#pragma unroll
                    for (int mt = 0; mt < 4; mt++)
#pragma unroll
                        for (int g = 0; g < 4; g++) {
                            mma_bf16(acc[mt][2 * g + 0], a[mt], &b[g][0]);
                            mma_bf16(acc[mt][2 * g + 1], a[mt], &b[g][2]);
                        }
                }
            }
        }
        __syncthreads();
        if (++jp == NPAIR) { jp = 0; ch++; }
    }

    const int prow0 = bb * SPAD + (row0 & 2047) + 1;
    if (ga.outMode[z] == 0) {
        __half* __restrict__ Chi = ga.Ch[z];
        __half* __restrict__ Clo = ga.Cl[z];
#pragma unroll
        for (int mt = 0; mt < 4; mt++) {
            int rl = wm + mt * 16 + (lane >> 2);
#pragma unroll
            for (int nt = 0; nt < 8; nt++) {
                int c = col0 + wn + nt * 8 + ((lane & 3) << 1);
                float2 bv = *(const float2*)&bP[c];
                uint32_t h2, l2;
                split_pair_f16(acc[mt][nt][0] + bv.x, acc[mt][nt][1] + bv.y, h2, l2);
                size_t o0 = ((size_t)(prow0 + rl) << 10) + c;
                *(uint32_t*)&Chi[o0] = h2;
                *(uint32_t*)&Clo[o0] = l2;
                split_pair_f16(acc[mt][nt][2] + bv.x, acc[mt][nt][3] + bv.y, h2, l2);
                size_t o1 = ((size_t)(prow0 + rl + 8) << 10) + c;
                *(uint32_t*)&Chi[o1] = h2;
                *(uint32_t*)&Clo[o1] = l2;
            }
        }
    } else {
        __half* __restrict__ Cv = ga.Ch[z];
#pragma unroll
        for (int mt = 0; mt < 4; mt++) {
            int rl = wm + mt * 16 + (lane >> 2);
#pragma unroll
            for (int nt = 0; nt < 8; nt++) {
                int c = col0 + wn + nt * 8 + ((lane & 3) << 1);
                float2 bv = *(const float2*)&bP[c];
                uint32_t p0 = pack_f16(acc[mt][nt][0] + bv.x, acc[mt][nt][1] + bv.y);
                uint32_t p1 = pack_f16(acc[mt][nt][2] + bv.x, acc[mt][nt][3] + bv.y);
                *(uint32_t*)&Cv[((size_t)(prow0 + rl) << 10) + c] = p0;
                *(uint32_t*)&Cv[((size_t)(prow0 + rl + 8) << 10) + c] = p1;
            }
        }
    }
}

// ===========================================================================
// Small fp16 GEMM (R16 version, f16 path) — used for v projection and the
// output linear. BM=128, BN=128, 2 CTAs/SM.
// ===========================================================================
#define G4_AMAT 18720
#define G4_ABUF (2 * G4_AMAT)
#define G4_AREG (2 * G4_ABUF)
#define G4_BTILE 18432
#define GEMM_SMEM (G4_AREG + 2 * G4_BTILE)

struct GArgs {
    const __half* Af;
    const __half* Bw; const float* bias;
    __half* Ch;
    float* Cf;
    int outMode;      // 1: fp16 (padded rows), 2: fp32 dense
};

__global__ void __launch_bounds__(256, 2) gemm_hmma_kernel(GArgs ga)
{
    extern __shared__ __align__(128) char smem[];
    const uint32_t sb = smem_to_u32(smem);
    const int tid = threadIdx.x, wid = tid >> 5, lane = tid & 31;
    const __half* __restrict__ Af = ga.Af;
    const __half* __restrict__ Bw = ga.Bw;
    const float* __restrict__ bP = ga.bias;

    const int row0 = blockIdx.y << 7;
    const int col0 = blockIdx.x << 7;
    const int bb = row0 >> 11;
    const size_t base = (size_t)bb * SPAD + (row0 & 2047);
    const int Kp = 1024;
    const int J = 16;
    const int wm = (wid >> 1) << 5;
    const int wn = (wid & 1) << 6;

    auto load_A = [&](int ch) {
        uint32_t dst = sb + (uint32_t)(ch & 1) * G4_ABUF;
        int c0 = ch << 6;
#pragma unroll
        for (int l = 0; l < 5; l++) {
            int idx = tid + (l << 8);
            if (idx < 1040) {
                int r = idx >> 3, jc = idx & 7;
                cp16(dst + (uint32_t)(r * 144 + (jc << 4)),
                     Af + (((base + r) << 10) + c0 + (jc << 3)));
            }
        }
    };
    auto load_B = [&](int j, int ch) {
        uint32_t dst = sb + G4_AREG + (uint32_t)(j & 1) * G4_BTILE;
        size_t k0 = (size_t)ch << 6;
#pragma unroll
        for (int l = 0; l < 4; l++) {
            int idx = tid + (l << 8);
            int r = idx >> 3, jc = idx & 7;
            cp16(dst + (uint32_t)(r * 144 + (jc << 4)),
                 Bw + (size_t)(col0 + r) * Kp + k0 + (jc << 3));
        }
    };

    float acc[2][8][4];
#pragma unroll
    for (int mt = 0; mt < 2; mt++)
#pragma unroll
        for (int nt = 0; nt < 8; nt++)
#pragma unroll
            for (int e = 0; e < 4; e++) acc[mt][nt][e] = 0.f;

    load_A(0);
    load_B(0, 0);
    asm volatile("cp.async.commit_group;");

    for (int j = 0; j < J; j++) {
        if (j + 1 < J) {
            load_A(j + 1);
            load_B(j + 1, j + 1);
            asm volatile("cp.async.commit_group;");
            asm volatile("cp.async.wait_group 1;");
        } else {
            asm volatile("cp.async.commit_group;");
            asm volatile("cp.async.wait_group 0;");
        }
        __syncthreads();

        const uint32_t Asm = sb + (uint32_t)(j & 1) * G4_ABUF;
        const uint32_t Bsm = sb + G4_AREG + (uint32_t)(j & 1) * G4_BTILE;

#pragma unroll
        for (int kk = 0; kk < 64; kk += 16) {
            uint32_t b[4][4], a[2][4];
#pragma unroll
            for (int g = 0; g < 4; g++) {
                int nrow = wn + g * 16 + (lane & 7) + ((lane >> 4) << 3);
                ldsm_x4(b[g], Bsm + (uint32_t)(nrow * 144 + (kk + (((lane >> 3) & 1) << 3)) * 2));
            }
#pragma unroll
            for (int mt = 0; mt < 2; mt++)
                ldsm_x4(a[mt], Asm + (uint32_t)((wm + 1 + mt * 16 + (lane & 15)) * 144
                        + ((lane >> 4) << 4) + kk * 2));
#pragma unroll
            for (int mt = 0; mt < 2; mt++)
#pragma unroll
                for (int g = 0; g < 4; g++) {
                    mma_f16(acc[mt][2 * g + 0], a[mt], &b[g][0]);
                    mma_f16(acc[mt][2 * g + 1], a[mt], &b[g][2]);
                }
        }
        __syncthreads();
    }

    const int prow0 = bb * SPAD + (row0 & 2047) + 1;
    if (ga.outMode == 1) {
        __half* __restrict__ Cv = ga.Ch;
#pragma unroll
        for (int mt = 0; mt < 2; mt++) {
            int rl = wm + mt * 16 + (lane >> 2);
#pragma unroll
            for (int nt = 0; nt < 8; nt++) {
                int c = col0 + wn + nt * 8 + ((lane & 3) << 1);
                float2 bv = *(const float2*)&bP[c];
                uint32_t p0 = pack_f16(acc[mt][nt][0] + bv.x, acc[mt][nt][1] + bv.y);
                uint32_t p1 = pack_f16(acc[mt][nt][2] + bv.x, acc[mt][nt][3] + bv.y);
                *(uint32_t*)&Cv[((size_t)(prow0 + rl) << 10) + c] = p0;
                *(uint32_t*)&Cv[((size_t)(prow0 + rl + 8) << 10) + c] = p1;
            }
        }
    } else {
        float* __restrict__ Cf = ga.Cf;
#pragma unroll
        for (int mt = 0; mt < 2; mt++) {
            int r = row0 + wm + mt * 16 + (lane >> 2);
#pragma unroll
            for (int nt = 0; nt < 8; nt++) {
                int c = col0 + wn + nt * 8 + ((lane & 3) << 1);
                float2 bv = *(const float2*)&bP[c];
                *(float2*)&Cf[(size_t)r * 1024 + c] =
                    make_float2(acc[mt][nt][0] + bv.x, acc[mt][nt][1] + bv.y);
                *(float2*)&Cf[(size_t)(r + 8) * 1024 + c] =
                    make_float2(acc[mt][nt][2] + bv.x, acc[mt][nt][3] + bv.y);
            }
        }
    }
}

// ===========================================================================
// HMMA flash attention (R16 version — passing): QK 2-term fp16, PV fp16,
// 128-key KV chunks as two 64-key passes.
// ===========================================================================
#define AT_QREG 18432
#define AT_KVBUF 36864
#define AT_SMEM (AT_QREG + 2 * AT_KVBUF + 1024)   // 93184

__global__ void __launch_bounds__(256, 2) attn_hmma_kernel(
    const __half* __restrict__ Qh, const __half* __restrict__ Ql,
    const __half* __restrict__ Kf, const __half* __restrict__ Vf,
    __half* __restrict__ Of)
{
    extern __shared__ __align__(128) char smem[];
    const uint32_t sb = smem_to_u32(smem);
    const uint32_t sKV = sb + AT_QREG;
    float* rs2 = (float*)(smem + AT_QREG + 2 * AT_KVBUF);
    float* outcmb = (float*)(smem + AT_QREG);

    const int tid = threadIdx.x, wid = tid >> 5, lane = tid & 31;
    const int wm = (wid >> 1) << 4;
    const int wnk = (wid & 1) << 5;
    const int q0 = blockIdx.x << 6;
    const int h = blockIdx.y, b = blockIdx.z;
    const size_t hoff = (size_t)h * 64;
    const size_t rowbase = (size_t)b * SPAD + 1;

#pragma unroll
    for (int l = 0; l < 4; l++) {
        int mat = l >> 1;
        int r = (tid >> 3) + ((l & 1) << 5);
        int j = tid & 7;
        const __half* src = (mat ? Ql : Qh) + (((rowbase + q0 + r) << 10) + hoff + (j << 3));
        cp16(sb + (uint32_t)(mat * 9216 + r * 144 + j * 16), src);
    }
    asm volatile("cp.async.commit_group;");

    auto loadKV = [&](int c) {
        uint32_t dstb = sKV + (uint32_t)(c & 1) * AT_KVBUF;
        size_t krow = rowbase + ((size_t)c << 7);
#pragma unroll
        for (int l = 0; l < 8; l++) {
            int mat = l >> 2;
            int r = (tid >> 3) + ((l & 3) << 5);
            int j = tid & 7;
            const __half* src = (mat ? Vf : Kf) + (((krow + r) << 10) + hoff + (j << 3));
            cp16(dstb + (uint32_t)(mat * 18432 + r * 144 + j * 16), src);
        }
    };
    loadKV(0);
    asm volatile("cp.async.commit_group;");

    float outacc[8][4];
    float rs[2] = {0.f, 0.f};
#pragma unroll
    for (int nt = 0; nt < 8; nt++)
#pragma unroll
        for (int e = 0; e < 4; e++) outacc[nt][e] = 0.f;

    const float CEXP = 1.4426950408889634f * 0.125f;
    const float EBIAS = 17.312340490667562f;

    for (int c = 0; c < 16; c++) {
        if (c + 1 < 16) {
            loadKV(c + 1);
            asm volatile("cp.async.commit_group;");
            asm volatile("cp.async.wait_group 1;");
        } else {
            asm volatile("cp.async.wait_group 0;");
        }
        __syncthreads();
        uint32_t bufb = sKV + (uint32_t)(c & 1) * AT_KVBUF;

#pragma unroll
        for (int half = 0; half < 2; half++) {
            const uint32_t kbase = bufb + (uint32_t)(half << 6) * 144;
            const uint32_t vbase = bufb + 18432 + (uint32_t)(half << 6) * 144;

            float sc[4][4];
#pragma unroll
            for (int nt = 0; nt < 4; nt++)
#pragma unroll
                for (int e = 0; e < 4; e++) sc[nt][e] = 0.f;

#pragma unroll
            for (int ks = 0; ks < 4; ks++) {
                uint32_t ah[4], al[4], bk[2][4];
                uint32_t qaddr = sb + (uint32_t)((wm + (lane & 15)) * 144
                                 + ((lane >> 4) << 4) + ks * 32);
                ldsm_x4(ah, qaddr);
                ldsm_x4(al, qaddr + 9216);
#pragma unroll
                for (int g = 0; g < 2; g++) {
                    int nrow = wnk + g * 16 + (lane & 7) + ((lane >> 4) << 3);
                    ldsm_x4(bk[g], kbase + (uint32_t)(nrow * 144 + ks * 32 + (((lane >> 3) & 1) << 4)));
                }
#pragma unroll
                for (int g = 0; g < 2; g++) {
                    mma_f16(sc[2 * g + 0], ah, &bk[g][0]);
                    mma_f16(sc[2 * g + 1], ah, &bk[g][2]);
                    mma_f16(sc[2 * g + 0], al, &bk[g][0]);
                    mma_f16(sc[2 * g + 1], al, &bk[g][2]);
                }
            }

            uint32_t phi[2][4];
#pragma unroll
            for (int nt = 0; nt < 4; nt++)
#pragma unroll
                for (int e = 0; e < 4; e++) {
                    float p = ex2f(sc[nt][e] * CEXP - EBIAS);
                    sc[nt][e] = p;
                    rs[e >> 1] += p;
                }
#pragma unroll
            for (int kt = 0; kt < 2; kt++) {
                phi[kt][0] = pack_f16(sc[2 * kt][0], sc[2 * kt][1]);
                phi[kt][1] = pack_f16(sc[2 * kt][2], sc[2 * kt][3]);
                phi[kt][2] = pack_f16(sc[2 * kt + 1][0], sc[2 * kt + 1][1]);
                phi[kt][3] = pack_f16(sc[2 * kt + 1][2], sc[2 * kt + 1][3]);
            }

#pragma unroll
            for (int kt = 0; kt < 2; kt++) {
                uint32_t vh[4][4];
#pragma unroll
                for (int g = 0; g < 4; g++) {
                    int keyrow = wnk + kt * 16 + (lane & 7) + (((lane >> 3) & 1) << 3);
                    ldsm_x4_t(vh[g], vbase + (uint32_t)(keyrow * 144 + g * 32 + ((lane >> 4) << 4)));
                }
#pragma unroll
                for (int g = 0; g < 4; g++) {
                    mma_f16(outacc[2 * g + 0], phi[kt], &vh[g][0]);
                    mma_f16(outacc[2 * g + 1], phi[kt], &vh[g][2]);
                }
            }
        }
        __syncthreads();
    }

#pragma unroll
    for (int hf = 0; hf < 2; hf++) {
        rs[hf] += __shfl_xor_sync(0xffffffffu, rs[hf], 1);
        rs[hf] += __shfl_xor_sync(0xffffffffu, rs[hf], 2);
    }
    if ((lane & 3) == 0) {
#pragma unroll
        for (int hf = 0; hf < 2; hf++)
            rs2[(wm + (lane >> 2) + hf * 8) * 2 + (wid & 1)] = rs[hf];
    }
    if (wid & 1) {
#pragma unroll
        for (int nt = 0; nt < 8; nt++)
#pragma unroll
            for (int e = 0; e < 4; e++) {
                int row = wm + (lane >> 2) + (e >> 1) * 8;
                int col = nt * 8 + ((lane & 3) << 1) + (e & 1);
                outcmb[row * 66 + col] = outacc[nt][e];
            }
    }
    __syncthreads();
    if (!(wid & 1)) {
        int r0 = wm + (lane >> 2);
#pragma unroll
        for (int hf = 0; hf < 2; hf++) {
            int row = r0 + hf * 8;
            float inv = 1.f / (rs2[row * 2] + rs2[row * 2 + 1]);
            size_t grow = ((rowbase + q0 + row) << 10) + hoff;
#pragma unroll
            for (int nt = 0; nt < 8; nt++) {
                int col = nt * 8 + ((lane & 3) << 1);
                float v0 = (outacc[nt][hf * 2 + 0] + outcmb[row * 66 + col]) * inv;
                float v1 = (outacc[nt][hf * 2 + 1] + outcmb[row * 66 + col + 1]) * inv;
                *(uint32_t*)&Of[grow + col] = pack_f16(v0, v1);
            }
        }
    }
}

// ===========================================================================
// Launch
// ===========================================================================
extern "C" void kernel_launch(void* const* d_in, const int* in_sizes, int n_in,
                              void* d_out, int out_size) {
    const float* q    = (const float*)d_in[0];
    const float* k    = (const float*)d_in[1];
    const float* v    = (const float*)d_in[2];
    const float* wq_w = (const float*)d_in[3];
    const float* wq_b = (const float*)d_in[4];
    const float* wk_w = (const float*)d_in[5];
    const float* wk_b = (const float*)d_in[6];
    const float* wv_w = (const float*)d_in[7];
    const float* wv_b = (const float*)d_in[8];
    const float* wc_w = (const float*)d_in[9];
    const float* wc_b = (const float*)d_in[10];

    __nv_bfloat16 *pHi, *pLo, *pWq, *pWk;
    __half *pVact, *pQfh, *pQfl, *pKf, *pVf, *pAOf, *pWvf, *pWcf;
    float *pbq, *pbk, *pbv, *pbc;
    cudaGetSymbolAddress((void**)&pHi, g_hi);
    cudaGetSymbolAddress((void**)&pLo, g_lo);
    cudaGetSymbolAddress((void**)&pVact, g_vact);
    cudaGetSymbolAddress((void**)&pQfh, g_qfh);
    cudaGetSymbolAddress((void**)&pQfl, g_qfl);
    cudaGetSymbolAddress((void**)&pKf, g_kf);
    cudaGetSymbolAddress((void**)&pVf, g_vf);
    cudaGetSymbolAddress((void**)&pAOf, g_aof);
    cudaGetSymbolAddress((void**)&pWq, g_Wqc);
    cudaGetSymbolAddress((void**)&pWk, g_Wkc);
    cudaGetSymbolAddress((void**)&pWvf, g_Wvf);
    cudaGetSymbolAddress((void**)&pWcf, g_Wcf);
    cudaGetSymbolAddress((void**)&pbq, g_bq);
    cudaGetSymbolAddress((void**)&pbk, g_bk);
    cudaGetSymbolAddress((void**)&pbv, g_bv);
    cudaGetSymbolAddress((void**)&pbc, g_bc);

    const int TSLOT = PADROWS * DMODEL;

    cudaFuncSetAttribute(gemm_qk_kernel, cudaFuncAttributeMaxDynamicSharedMemorySize, QK_SMEM);
    cudaFuncSetAttribute(gemm_hmma_kernel, cudaFuncAttributeMaxDynamicSharedMemorySize, GEMM_SMEM);
    cudaFuncSetAttribute(attn_hmma_kernel, cudaFuncAttributeMaxDynamicSharedMemorySize, AT_SMEM);

    // 1) fused activation split
    SArgs sa;
    sa.X[0] = q; sa.X[1] = k; sa.X[2] = v;
    for (int t = 0; t < 2; t++) { sa.hi[t] = pHi + t * TSLOT; sa.lo[t] = pLo + t * TSLOT; }
    sa.vf = pVact;
    split_act_all<<<dim3(1, (SPAD + 3) / 4, 6), 256>>>(sa);

    // 2) fused weight transforms
    WArgs wa;
    wa.w[0] = wq_w; wa.w[1] = wk_w; wa.w[2] = wv_w; wa.w[3] = wc_w;
    wa.b[0] = wq_b; wa.b[1] = wk_b; wa.b[2] = wv_b; wa.b[3] = wc_b;
    wa.out[0] = pWq; wa.out[1] = pWk; wa.out[2] = pWvf; wa.out[3] = pWcf;
    wa.bP[0] = pbq; wa.bP[1] = pbk; wa.bP[2] = pbv; wa.bP[3] = pbc;
    wa.KS[0] = 3; wa.KS[1] = 3; wa.KS[2] = 1; wa.KS[3] = 1;
    wa.perm[0] = 1; wa.perm[1] = 1; wa.perm[2] = 1; wa.perm[3] = 0;
    wa.f16[0] = 0; wa.f16[1] = 0; wa.f16[2] = 1; wa.f16[3] = 1;
    transform_w_all<<<dim3(DMODEL, 4), 256>>>(wa);

    // 3a) q/k projections via BM=256 wide-B kernel (half the sync points)
    QKArgs gqk = {};
    gqk.Ah[0] = pHi + 0 * TSLOT; gqk.Al[0] = pLo + 0 * TSLOT;
    gqk.Ah[1] = pHi + 1 * TSLOT; gqk.Al[1] = pLo + 1 * TSLOT;
    gqk.Bw[0] = pWq; gqk.Bw[1] = pWk;
    gqk.bias[0] = pbq; gqk.bias[1] = pbk;
    gqk.Ch[0] = pQfh; gqk.Cl[0] = pQfl;
    gqk.Ch[1] = pKf;  gqk.Cl[1] = nullptr;
    gqk.outMode[0] = 0; gqk.outMode[1] = 1;
    gemm_qk_kernel<<<dim3(DMODEL / 128, (BATCH * SEQ) / 256, 2), 256, QK_SMEM>>>(gqk);

    // 3b) v projection (fp16 single)
    GArgs gv = {};
    gv.Af = pVact; gv.Bw = pWvf; gv.bias = pbv;
    gv.Ch = pVf; gv.outMode = 1;
    gemm_hmma_kernel<<<dim3(DMODEL / 128, (BATCH * SEQ) / 128, 1), 256, GEMM_SMEM>>>(gv);

    // 4) HMMA attention
    dim3 gattn(SEQ / 64, NHEAD, BATCH);
    attn_hmma_kernel<<<gattn, 256, AT_SMEM>>>(pQfh, pQfl, pKf, pVf, pAOf);

    // 5) output linear -> d_out (fp32)
    GArgs gc = {};
    gc.Af = pAOf; gc.Bw = pWcf; gc.bias = pbc;
    gc.Cf = (float*)d_out; gc.outMode = 2;
    gemm_hmma_kernel<<<dim3(DMODEL / 128, (BATCH * SEQ) / 128, 1), 256, GEMM_SMEM>>>(gc);
}